// round 1
// baseline (speedup 1.0000x reference)
#include <cuda_runtime.h>
#include <cuda_bf16.h>

#define FAR_DIST 1e10f
#define EPS_K    1e-10f

// One warp per ray. Lane l handles samples {c*32 + l}. Exclusive cumprod of
// (1 - alpha + EPS) done via chunked warp inclusive scans + scalar carry.
__global__ __launch_bounds__(256) void Render_kernel(
    const float* __restrict__ rgb_raw,   // [B, N, 3]
    const float* __restrict__ density,   // [B, N, 1]
    const float* __restrict__ z_vals,    // [B, N]
    const float* __restrict__ dir,       // [B, 3]
    float* __restrict__ out_rgb,         // [B, 3]
    float* __restrict__ out_w,           // [B, N]
    float* __restrict__ out_depth,       // [B]
    float* __restrict__ out_acc,         // [B]
    float* __restrict__ out_disp,        // [B]
    int B, int N)
{
    const int warp_global = (blockIdx.x * blockDim.x + threadIdx.x) >> 5;
    const int lane = threadIdx.x & 31;
    if (warp_global >= B) return;
    const int ray = warp_global;

    // ray direction norm (3 scalar loads, L1-broadcast across the warp)
    const float dx = dir[ray * 3 + 0];
    const float dy = dir[ray * 3 + 1];
    const float dz = dir[ray * 3 + 2];
    const float dnorm = sqrtf(dx * dx + dy * dy + dz * dz);

    const float* __restrict__ zr = z_vals  + (size_t)ray * N;
    const float* __restrict__ dr = density + (size_t)ray * N;
    const float* __restrict__ cr = rgb_raw + (size_t)ray * N * 3;
    float* __restrict__       wr = out_w   + (size_t)ray * N;

    float carry = 1.0f;               // product of (1-alpha+eps) over all prior chunks
    float acc_r = 0.f, acc_g = 0.f, acc_b = 0.f;
    float acc_depth = 0.f, acc_w = 0.f;

    const int chunks = (N + 31) >> 5;
    for (int c = 0; c < chunks; ++c) {
        const int s = (c << 5) + lane;
        const bool active = (s < N);

        float z = 0.f, dist = 0.f, dval = 0.f;
        if (active) {
            z = zr[s];
            const float znext = (s + 1 < N) ? zr[s + 1] : 0.f;
            dist = ((s + 1 < N) ? (znext - z) : FAR_DIST) * dnorm;
            dval = dr[s];
        }

        // alpha = 1 - exp(-relu(density)*dist);  t = (1 - alpha) + EPS
        const float e = __expf(-fmaxf(dval, 0.f) * dist);
        const float alpha = active ? (1.0f - e) : 0.0f;
        float t = active ? (e + EPS_K) : 1.0f;

        // warp inclusive scan (product) of t in sample order
        float incl = t;
        #pragma unroll
        for (int off = 1; off < 32; off <<= 1) {
            const float v = __shfl_up_sync(0xffffffffu, incl, off);
            if (lane >= off) incl *= v;
        }
        float excl = __shfl_up_sync(0xffffffffu, incl, 1);
        if (lane == 0) excl = 1.0f;

        const float trans = carry * excl;
        carry *= __shfl_sync(0xffffffffu, incl, 31);

        if (active) {
            const float w = alpha * trans;
            wr[s] = w;

            // sigmoid(rgb_raw)
            const float c0 = cr[s * 3 + 0];
            const float c1 = cr[s * 3 + 1];
            const float c2 = cr[s * 3 + 2];
            const float s0 = 1.0f / (1.0f + __expf(-c0));
            const float s1 = 1.0f / (1.0f + __expf(-c1));
            const float s2 = 1.0f / (1.0f + __expf(-c2));

            acc_r     += w * s0;
            acc_g     += w * s1;
            acc_b     += w * s2;
            acc_depth += w * z;
            acc_w     += w;
        }
    }

    // warp reductions (5 values)
    #pragma unroll
    for (int off = 16; off; off >>= 1) {
        acc_r     += __shfl_xor_sync(0xffffffffu, acc_r, off);
        acc_g     += __shfl_xor_sync(0xffffffffu, acc_g, off);
        acc_b     += __shfl_xor_sync(0xffffffffu, acc_b, off);
        acc_depth += __shfl_xor_sync(0xffffffffu, acc_depth, off);
        acc_w     += __shfl_xor_sync(0xffffffffu, acc_w, off);
    }

    if (lane == 0) {
        out_rgb[ray * 3 + 0] = acc_r;
        out_rgb[ray * 3 + 1] = acc_g;
        out_rgb[ray * 3 + 2] = acc_b;
        out_depth[ray] = acc_depth;
        out_acc[ray]   = acc_w;
        out_disp[ray]  = 1.0f / fmaxf(EPS_K, acc_depth / acc_w);
    }
}

extern "C" void kernel_launch(void* const* d_in, const int* in_sizes, int n_in,
                              void* d_out, int out_size) {
    const float* rgb_raw = (const float*)d_in[0];
    const float* density = (const float*)d_in[1];
    const float* z_vals  = (const float*)d_in[2];
    const float* dir     = (const float*)d_in[3];

    const int B = in_sizes[3] / 3;          // dir is [B,3]
    const int N = in_sizes[2] / B;          // z_vals is [B,N]

    float* out       = (float*)d_out;
    float* out_rgb   = out;                                  // [B,3]
    float* out_w     = out_rgb + (size_t)B * 3;              // [B,N]
    float* out_depth = out_w   + (size_t)B * N;              // [B]
    float* out_acc   = out_depth + B;                        // [B]
    float* out_disp  = out_acc   + B;                        // [B]

    const int warps_per_block = 8;
    const int threads = warps_per_block * 32;
    const int blocks = (B + warps_per_block - 1) / warps_per_block;

    Render_kernel<<<blocks, threads>>>(rgb_raw, density, z_vals, dir,
                                       out_rgb, out_w, out_depth, out_acc, out_disp,
                                       B, N);
}

// round 3
// speedup vs baseline: 1.6580x; 1.6580x over previous
#include <cuda_runtime.h>
#include <cuda_bf16.h>

#define FAR_DIST 1e10f
#define EPS_K    1e-10f

__device__ __forceinline__ float sigmoid_fast(float x) {
    return __fdividef(1.0f, 1.0f + __expf(-x));
}

// Specialized N=192 path: one warp per ray, lane l owns samples [6l, 6l+6).
// All global accesses are float2-vectorized and contiguous per warp.
// Single 5-step warp scan over per-lane partial products replaces chunked scans.
__global__ __launch_bounds__(256) void render_n192(
    const float* __restrict__ rgb_raw,   // [B, 192, 3]
    const float* __restrict__ density,   // [B, 192, 1]
    const float* __restrict__ z_vals,    // [B, 192]
    const float* __restrict__ dir,       // [B, 3]
    float* __restrict__ out_rgb,         // [B, 3]
    float* __restrict__ out_w,           // [B, 192]
    float* __restrict__ out_depth,       // [B]
    float* __restrict__ out_acc,         // [B]
    float* __restrict__ out_disp,        // [B]
    int B)
{
    constexpr int N = 192;
    const int ray  = (blockIdx.x * blockDim.x + threadIdx.x) >> 5;
    const int lane = threadIdx.x & 31;
    if (ray >= B) return;

    const float dx = dir[ray * 3 + 0];
    const float dy = dir[ray * 3 + 1];
    const float dz = dir[ray * 3 + 2];
    const float dnorm = sqrtf(dx * dx + dy * dy + dz * dz);

    const size_t sbase = (size_t)ray * N + lane * 6;

    // z samples (6 per lane), density (6 per lane): contiguous float2 loads
    const float2 za = *(const float2*)(z_vals + sbase);
    const float2 zb = *(const float2*)(z_vals + sbase + 2);
    const float2 zc = *(const float2*)(z_vals + sbase + 4);
    const float2 ga = *(const float2*)(density + sbase);
    const float2 gb = *(const float2*)(density + sbase + 2);
    const float2 gc = *(const float2*)(density + sbase + 4);

    // rgb: 18 floats per lane, 9 float2 loads (8B-aligned: 72*lane)
    const float* __restrict__ cr = rgb_raw + sbase * 3;
    float c[18];
    #pragma unroll
    for (int i = 0; i < 9; ++i) {
        const float2 v = *(const float2*)(cr + 2 * i);
        c[2 * i] = v.x; c[2 * i + 1] = v.y;
    }

    const float z0 = za.x, z1 = za.y, z2 = zb.x, z3 = zb.y, z4 = zc.x, z5 = zc.y;

    // z of neighbor lane's first sample = z[6l+6]
    const float zn = __shfl_down_sync(0xffffffffu, z0, 1);

    float dist[6];
    dist[0] = (z1 - z0) * dnorm;
    dist[1] = (z2 - z1) * dnorm;
    dist[2] = (z3 - z2) * dnorm;
    dist[3] = (z4 - z3) * dnorm;
    dist[4] = (z5 - z4) * dnorm;
    dist[5] = ((lane == 31) ? FAR_DIST : (zn - z5)) * dnorm;

    const float den[6] = {ga.x, ga.y, gb.x, gb.y, gc.x, gc.y};

    float t[6], alpha[6];
    #pragma unroll
    for (int i = 0; i < 6; ++i) {
        const float e = __expf(-fmaxf(den[i], 0.0f) * dist[i]);
        alpha[i] = 1.0f - e;
        t[i]     = e + EPS_K;
    }

    // local inclusive products p[i] = t0*...*ti
    const float p0 = t[0];
    const float p1 = p0 * t[1];
    const float p2 = p1 * t[2];
    const float p3 = p2 * t[3];
    const float p4 = p3 * t[4];
    const float p5 = p4 * t[5];

    // single warp scan over lane totals
    float incl = p5;
    #pragma unroll
    for (int off = 1; off < 32; off <<= 1) {
        const float v = __shfl_up_sync(0xffffffffu, incl, off);
        if (lane >= off) incl *= v;
    }
    float excl = __shfl_up_sync(0xffffffffu, incl, 1);
    if (lane == 0) excl = 1.0f;

    // per-sample transmittance and weights
    const float T0 = excl;
    const float T1 = excl * p0;
    const float T2 = excl * p1;
    const float T3 = excl * p2;
    const float T4 = excl * p3;
    const float T5 = excl * p4;

    float w[6];
    w[0] = alpha[0] * T0;
    w[1] = alpha[1] * T1;
    w[2] = alpha[2] * T2;
    w[3] = alpha[3] * T3;
    w[4] = alpha[4] * T4;
    w[5] = alpha[5] * T5;

    // store weights (float2-vectorized)
    float* __restrict__ wr = out_w + sbase;
    *(float2*)(wr)     = make_float2(w[0], w[1]);
    *(float2*)(wr + 2) = make_float2(w[2], w[3]);
    *(float2*)(wr + 4) = make_float2(w[4], w[5]);

    // accumulate outputs
    const float zv[6] = {z0, z1, z2, z3, z4, z5};
    float ar = 0.f, ag = 0.f, ab = 0.f, adep = 0.f, aw = 0.f;
    #pragma unroll
    for (int i = 0; i < 6; ++i) {
        ar   += w[i] * sigmoid_fast(c[3 * i + 0]);
        ag   += w[i] * sigmoid_fast(c[3 * i + 1]);
        ab   += w[i] * sigmoid_fast(c[3 * i + 2]);
        adep += w[i] * zv[i];
        aw   += w[i];
    }

    #pragma unroll
    for (int off = 16; off; off >>= 1) {
        ar   += __shfl_xor_sync(0xffffffffu, ar,   off);
        ag   += __shfl_xor_sync(0xffffffffu, ag,   off);
        ab   += __shfl_xor_sync(0xffffffffu, ab,   off);
        adep += __shfl_xor_sync(0xffffffffu, adep, off);
        aw   += __shfl_xor_sync(0xffffffffu, aw,   off);
    }

    if (lane == 0) {
        out_rgb[ray * 3 + 0] = ar;
        out_rgb[ray * 3 + 1] = ag;
        out_rgb[ray * 3 + 2] = ab;
        out_depth[ray] = adep;
        out_acc[ray]   = aw;
        out_disp[ray]  = 1.0f / fmaxf(EPS_K, adep / aw);
    }
}

// ---------------- generic fallback (any N) — round-1 kernel ----------------
__global__ __launch_bounds__(256) void render_generic(
    const float* __restrict__ rgb_raw, const float* __restrict__ density,
    const float* __restrict__ z_vals, const float* __restrict__ dir,
    float* __restrict__ out_rgb, float* __restrict__ out_w,
    float* __restrict__ out_depth, float* __restrict__ out_acc,
    float* __restrict__ out_disp, int B, int N)
{
    const int ray  = (blockIdx.x * blockDim.x + threadIdx.x) >> 5;
    const int lane = threadIdx.x & 31;
    if (ray >= B) return;

    const float dx = dir[ray * 3 + 0], dy = dir[ray * 3 + 1], dz = dir[ray * 3 + 2];
    const float dnorm = sqrtf(dx * dx + dy * dy + dz * dz);

    const float* __restrict__ zr = z_vals  + (size_t)ray * N;
    const float* __restrict__ dr = density + (size_t)ray * N;
    const float* __restrict__ cr = rgb_raw + (size_t)ray * N * 3;
    float* __restrict__       wr = out_w   + (size_t)ray * N;

    float carry = 1.0f;
    float ar = 0.f, ag = 0.f, ab = 0.f, adep = 0.f, aw = 0.f;

    const int chunks = (N + 31) >> 5;
    for (int cc = 0; cc < chunks; ++cc) {
        const int s = (cc << 5) + lane;
        const bool active = (s < N);
        float z = 0.f, dist = 0.f, dval = 0.f;
        if (active) {
            z = zr[s];
            const float znext = (s + 1 < N) ? zr[s + 1] : 0.f;
            dist = ((s + 1 < N) ? (znext - z) : FAR_DIST) * dnorm;
            dval = dr[s];
        }
        const float e = __expf(-fmaxf(dval, 0.f) * dist);
        const float alpha = active ? (1.0f - e) : 0.0f;
        float t = active ? (e + EPS_K) : 1.0f;

        float incl = t;
        #pragma unroll
        for (int off = 1; off < 32; off <<= 1) {
            const float v = __shfl_up_sync(0xffffffffu, incl, off);
            if (lane >= off) incl *= v;
        }
        float excl = __shfl_up_sync(0xffffffffu, incl, 1);
        if (lane == 0) excl = 1.0f;
        const float trans = carry * excl;
        carry *= __shfl_sync(0xffffffffu, incl, 31);

        if (active) {
            const float w = alpha * trans;
            wr[s] = w;
            const float s0 = sigmoid_fast(cr[s * 3 + 0]);
            const float s1 = sigmoid_fast(cr[s * 3 + 1]);
            const float s2 = sigmoid_fast(cr[s * 3 + 2]);
            ar += w * s0; ag += w * s1; ab += w * s2;
            adep += w * z; aw += w;
        }
    }
    #pragma unroll
    for (int off = 16; off; off >>= 1) {
        ar   += __shfl_xor_sync(0xffffffffu, ar,   off);
        ag   += __shfl_xor_sync(0xffffffffu, ag,   off);
        ab   += __shfl_xor_sync(0xffffffffu, ab,   off);
        adep += __shfl_xor_sync(0xffffffffu, adep, off);
        aw   += __shfl_xor_sync(0xffffffffu, aw,   off);
    }
    if (lane == 0) {
        out_rgb[ray * 3 + 0] = ar;
        out_rgb[ray * 3 + 1] = ag;
        out_rgb[ray * 3 + 2] = ab;
        out_depth[ray] = adep;
        out_acc[ray]   = aw;
        out_disp[ray]  = 1.0f / fmaxf(EPS_K, adep / aw);
    }
}

extern "C" void kernel_launch(void* const* d_in, const int* in_sizes, int n_in,
                              void* d_out, int out_size) {
    const float* rgb_raw = (const float*)d_in[0];
    const float* density = (const float*)d_in[1];
    const float* z_vals  = (const float*)d_in[2];
    const float* dir     = (const float*)d_in[3];

    const int B = in_sizes[3] / 3;
    const int N = in_sizes[2] / B;

    float* out       = (float*)d_out;
    float* out_rgb   = out;
    float* out_w     = out_rgb + (size_t)B * 3;
    float* out_depth = out_w   + (size_t)B * N;
    float* out_acc   = out_depth + B;
    float* out_disp  = out_acc   + B;

    const int warps_per_block = 8;
    const int threads = warps_per_block * 32;
    const int blocks = (B + warps_per_block - 1) / warps_per_block;

    if (N == 192) {
        render_n192<<<blocks, threads>>>(rgb_raw, density, z_vals, dir,
                                         out_rgb, out_w, out_depth, out_acc, out_disp, B);
    } else {
        render_generic<<<blocks, threads>>>(rgb_raw, density, z_vals, dir,
                                            out_rgb, out_w, out_depth, out_acc, out_disp, B, N);
    }
}